// round 17
// baseline (speedup 1.0000x reference)
#include <cuda_runtime.h>
#include <cuda_fp16.h>
#include <math.h>

// ---------------------------------------------------------------------------
// SiamFC head, round 17: R16 with full 64-channel loop (cb<16 fix).
//   H[b,r,j,p] = sum_{c,q} x'[b,c,r-8,j+q-8] * z'[b,c,p,q]   (HMMA f16-acc)
//   out[b,i,j] = 0.001 * sum_p H[b,i+p,j,p]                  (fused via RED)
// corr: 2 rows/CTA, 4 warps = (row, j-half); even+odd shifted smem copies
// make each B-frag reg one aligned LDS.32 (no shifts); depth-4 A prefetch;
// f16->f32 flush every 8 c; RED scatter epilogue.
// ---------------------------------------------------------------------------

__device__ __align__(16) unsigned XG[64 * 64 * 112 * 56];     // x' fp16 half2 words
__device__ __align__(16) unsigned ZA[(64 * 64 + 8) * 128];    // z' A-frag order (+pad)

// Fast exact-GELU: erf via Abramowitz-Stegun 7.1.26 (|err| <= 1.5e-7 abs).
__device__ __forceinline__ float gelu_fast(float v) {
    float s = fabsf(v) * 0.70710678118654752f;
    float t = __frcp_rn(fmaf(0.3275911f, s, 1.0f));
    float p = fmaf(1.061405429f, t, -1.453152027f);
    p = fmaf(p, t, 1.421413741f);
    p = fmaf(p, t, -0.284496736f);
    p = fmaf(p, t, 0.254829592f);
    p = p * t;
    float erfabs = fmaf(-p, __expf(-s * s), 1.0f);
    float erfs = copysignf(erfabs, v);
    return 0.5f * v * (1.0f + erfs);
}

__device__ __forceinline__ void red_add(float* p, float v) {
    asm volatile("red.global.add.f32 [%0], %1;" :: "l"(p), "f"(v) : "memory");
}

// ---- Kernel A: preprocess x -> XG ---------------------------------------------
__global__ __launch_bounds__(192) void prep_x(const float* __restrict__ x,
                                              const float* __restrict__ wx,
                                              const float* __restrict__ bx) {
    int bc = blockIdx.x;        // b*64 + c
    int c  = bc & 63;
    int tid = threadIdx.x;
    __shared__ __align__(16) float sp[98 * 100];

    float4 z4 = make_float4(0.f, 0.f, 0.f, 0.f);
    for (int i = tid; i < 2450; i += 192) reinterpret_cast<float4*>(sp)[i] = z4;
    __syncthreads();

    {
        int col = (tid < 96) ? tid : tid - 96;
        int rp  = (tid < 96) ? 0 : 1;
        const float* xp = x + (size_t)bc * 9216;
        for (int k = 0; k < 48; ++k) {
            int r = 2 * k + rp;
            sp[(r + 1) * 100 + (col + 1)] = xp[r * 96 + col];
        }
    }
    __syncthreads();

    float w[9];
#pragma unroll
    for (int k = 0; k < 9; ++k) w[k] = __ldg(wx + c * 9 + k);
    float bias = __ldg(bx + c);

    int v4 = tid % 12;
    int r0 = tid / 12;
    int xc0 = v4 * 8;

    uint4* dst = reinterpret_cast<uint4*>(XG + (size_t)bc * (112 * 56));
#pragma unroll 1
    for (int it = 0; it < 6; ++it) {
        int r = r0 + 16 * it;
        float rowv[3][12];
#pragma unroll
        for (int di = 0; di < 3; ++di) {
            const float4* src = reinterpret_cast<const float4*>(sp + (r + di) * 100 + xc0);
            float4 A = src[0], B = src[1], C = src[2];
            rowv[di][0] = A.x; rowv[di][1] = A.y; rowv[di][2]  = A.z; rowv[di][3]  = A.w;
            rowv[di][4] = B.x; rowv[di][5] = B.y; rowv[di][6]  = B.z; rowv[di][7]  = B.w;
            rowv[di][8] = C.x; rowv[di][9] = C.y; rowv[di][10] = C.z; rowv[di][11] = C.w;
        }
        unsigned ow[4];
#pragma unroll
        for (int t = 0; t < 4; ++t) {
            float f[2];
#pragma unroll
            for (int u = 0; u < 2; ++u) {
                int e = 2 * t + u;
                float conv = bias;
#pragma unroll
                for (int di = 0; di < 3; ++di)
#pragma unroll
                    for (int dj = 0; dj < 3; ++dj)
                        conv = fmaf(w[di * 3 + dj], rowv[di][e + dj], conv);
                f[u] = gelu_fast(rowv[1][e + 1] + conv);
            }
            __half2 h = __floats2half2_rn(f[0], f[1]);
            ow[t] = *reinterpret_cast<unsigned*>(&h);
        }
        dst[(r + 8) * 14 + 1 + v4] = make_uint4(ow[0], ow[1], ow[2], ow[3]);
    }
}

// ---- Kernel B: preprocess z -> ZA (A-frag order) + zero-init out ----------------
__global__ __launch_bounds__(256) void prep_z(const float* __restrict__ z,
                                              const float* __restrict__ wz,
                                              const float* __restrict__ bz,
                                              float* __restrict__ out, int n4) {
    int bc = blockIdx.x;
    int c  = bc & 63;
    __shared__ float sp[18 * 18];

    // fused zero-init of out (each block clears its slice)
    {
        float4 z4 = make_float4(0.f, 0.f, 0.f, 0.f);
        for (int i = blockIdx.x * 256 + threadIdx.x; i < n4; i += 4096 * 256)
            reinterpret_cast<float4*>(out)[i] = z4;
    }

    for (int i = threadIdx.x; i < 18 * 18; i += 256) sp[i] = 0.0f;
    __syncthreads();

    int t = threadIdx.x;
    int p = t >> 4, q = t & 15;
    sp[(p + 1) * 18 + (q + 1)] = z[(size_t)bc * 256 + t];
    __syncthreads();

    float conv = __ldg(bz + c);
#pragma unroll
    for (int di = 0; di < 3; ++di)
#pragma unroll
        for (int dj = 0; dj < 3; ++dj)
            conv = fmaf(__ldg(wz + c * 9 + di * 3 + dj), sp[(p + di) * 18 + (q + dj)], conv);
    float val = gelu_fast(sp[(p + 1) * 18 + (q + 1)] + conv);

    int lane = ((p & 7) << 2) | ((q & 7) >> 1);
    int reg  = ((p >> 3) & 1) | (((q >> 3) & 1) << 1);
    int h    = q & 1;
    reinterpret_cast<__half*>(ZA)[((size_t)bc * 32 + lane) * 8 + reg * 2 + h] =
        __float2half(val);
}

// ---- Kernel C: correlation GEMM + fused scatter epilogue ------------------------
// Grid (48, 64), 128 threads = 4 warps. Warp w: row = w&1, j-half = w>>1.
// smem layout (words): [row(2)][copy(2)][c(64)][word(64)] = 16384 words = 64 KB.
// Strides: row = 8192 words = 2048 uint4; copy = 4096 words = 1024 uint4.
// even copy word w = halves(2w, 2w+1); odd copy word w = halves(2w+1, 2w+2).
__global__ __launch_bounds__(128) void corr(float* __restrict__ out) {
    extern __shared__ unsigned sq[];
    int r0 = 8 + 2 * blockIdx.x, b = blockIdx.y;
    int tid = threadIdx.x, lane = tid & 31, w = tid >> 5;
    int row = w & 1, half = w >> 1;
    int r = r0 + row;
    int jt0 = half * 7;              // 0 or 7
    int ntile = 7 - half;            // 7 or 6

    // Stage even copies: 2 rows x 64 c x 16 uint4 (words 56..63 zero).
    for (int t = tid; t < 2048; t += 128) {
        int rw = t >> 10, g = t & 1023, c = g >> 4, v = g & 15;
        uint4 d = make_uint4(0u, 0u, 0u, 0u);
        if (v < 14)
            d = __ldg(reinterpret_cast<const uint4*>(XG) +
                      (size_t)(b * 64 + c) * 1568 + (size_t)(r0 + rw) * 14 + v);
        reinterpret_cast<uint4*>(sq)[rw * 2048 + (c << 4) + v] = d;
    }
    __syncthreads();
    // Build odd copies: word w = halves(2w+1, 2w+2), per 64-word c-block.
    for (int t = tid; t < 2048; t += 128) {
        int rw = t >> 10, g = t & 1023;
        int ebase = (rw << 13) + (g << 2);     // even copy word index
        uint4 ev = *reinterpret_cast<const uint4*>(sq + ebase);
        unsigned e4 = ((g & 15) == 15) ? 0u : sq[ebase + 4];
        uint4 o;
        o.x = __funnelshift_r(ev.x, ev.y, 16);
        o.y = __funnelshift_r(ev.y, ev.z, 16);
        o.z = __funnelshift_r(ev.z, ev.w, 16);
        o.w = __funnelshift_r(ev.w, e4, 16);
        reinterpret_cast<uint4*>(sq)[rw * 2048 + 1024 + g] = o;
    }
    __syncthreads();

    // Per-lane B-frag addressing: element e = nj + q0 (0..13).
    // Tile jt b0 word = 4*jt + (e>>1) in copy (e&1). b1 = b0 of jt+1.
    int nj = lane >> 2;
    int q0 = (lane & 3) << 1;
    int e  = nj + q0;
    const unsigned* base = sq + (row << 13) + ((e & 1) << 12) + (e >> 1) + (jt0 << 2);

    const uint4* zp = reinterpret_cast<const uint4*>(ZA) + (size_t)b * 64 * 32 + lane;

    float facc[7][4];
#pragma unroll
    for (int t = 0; t < 7; ++t)
#pragma unroll
        for (int k = 0; k < 4; ++k) facc[t][k] = 0.0f;

    unsigned hacc[7][2];
#pragma unroll
    for (int t = 0; t < 7; ++t) { hacc[t][0] = 0u; hacc[t][1] = 0u; }

    // Depth-4 A-fragment prefetch (ZA padded +8 blocks: c+4 <= 67 safe).
    uint4 abuf[4];
#pragma unroll
    for (int i = 0; i < 4; ++i) abuf[i] = __ldg(zp + i * 32);

#pragma unroll 1
    for (int cb = 0; cb < 16; ++cb) {      // FULL 64 channels (fix: was cb<8)
#pragma unroll
        for (int ci = 0; ci < 4; ++ci) {
            int c = 4 * cb + ci;
            uint4 a = abuf[ci];
            abuf[ci] = __ldg(zp + (c + 4) * 32);
            const unsigned* bc = base + (c << 6);
            unsigned cw = bc[0];
#pragma unroll
            for (int t = 0; t < 7; ++t) {
                unsigned nw = bc[4 * (t + 1)];
                if (t < ntile) {
                    asm volatile(
                        "mma.sync.aligned.m16n8k16.row.col.f16.f16.f16.f16 "
                        "{%0,%1}, {%2,%3,%4,%5}, {%6,%7}, {%0,%1};"
                        : "+r"(hacc[t][0]), "+r"(hacc[t][1])
                        : "r"(a.x), "r"(a.y), "r"(a.z), "r"(a.w), "r"(cw), "r"(nw));
                }
                cw = nw;
            }
        }
        if (cb & 1) {
            // Flush f16 fragments into fp32 accumulators (every 8 c)
#pragma unroll
            for (int t = 0; t < 7; ++t) {
                __half2 h0 = *reinterpret_cast<__half2*>(&hacc[t][0]);
                __half2 h1 = *reinterpret_cast<__half2*>(&hacc[t][1]);
                float2 f0 = __half22float2(h0);
                float2 f1 = __half22float2(h1);
                facc[t][0] += f0.x; facc[t][1] += f0.y;
                facc[t][2] += f1.x; facc[t][3] += f1.y;
                hacc[t][0] = 0u; hacc[t][1] = 0u;
            }
        }
    }

    // Fused epilogue: out[b, r-p, j] += 0.001 * H[p][j]
    int p0 = lane >> 2, jn = (lane & 3) << 1;
    float* ob = out + (size_t)b * 9409;
    int i_hi = r - p0;        // p = p0
    int i_lo = i_hi - 8;      // p = p0 + 8
#pragma unroll
    for (int t = 0; t < 7; ++t) {
        if (t < ntile) {
            int j = (jt0 + t) * 8 + jn;
            bool j0 = (j <= 96), j1 = (j < 96);
            if (i_hi <= 96) {
                if (j0) red_add(ob + i_hi * 97 + j,     facc[t][0] * 0.001f);
                if (j1) red_add(ob + i_hi * 97 + j + 1, facc[t][1] * 0.001f);
            }
            if (i_lo >= 0) {
                if (j0) red_add(ob + i_lo * 97 + j,     facc[t][2] * 0.001f);
                if (j1) red_add(ob + i_lo * 97 + j + 1, facc[t][3] * 0.001f);
            }
        }
    }
}

// ---- launch -----------------------------------------------------------------------
extern "C" void kernel_launch(void* const* d_in, const int* in_sizes, int n_in,
                              void* d_out, int out_size) {
    const float* z  = (const float*)d_in[0];
    const float* x  = (const float*)d_in[1];
    const float* wz = (const float*)d_in[2];
    const float* bz = (const float*)d_in[3];
    const float* wx = (const float*)d_in[4];
    const float* bx = (const float*)d_in[5];
    float* out = (float*)d_out;

    const int SMEM = 65536;
    cudaFuncSetAttribute(corr, cudaFuncAttributeMaxDynamicSharedMemorySize, SMEM);

    int n4 = out_size / 4;  // 150544
    prep_x<<<4096, 192>>>(x, wx, bx);
    prep_z<<<4096, 256>>>(z, wz, bz, out, n4);
    corr<<<dim3(48, 64), 128, SMEM>>>(out);
}